// round 14
// baseline (speedup 1.0000x reference)
#include <cuda_runtime.h>
#include <math.h>
#include <stdint.h>

// ---------------- device scratch ----------------
__device__ float g_xp[(size_t)2 * 512 * 1024 * 64];   // [dir][t][gate_row 0..1023][b]
__device__ float g_hP[(size_t)512 * 2 * 64 * 64 * 4]; // [t][d][jq][b][4]  (64MB)
__device__ float g_emis[(size_t)512 * 64 * 9];        // [t][b][tau]
__device__ float g_llh[64];
__device__ int   g_cnt[1024];                         // sub-counters: [d*512 + sub*32]

// ---------------- packed f32x2 helpers (Blackwell FFMA2) ----------------
__device__ __forceinline__ unsigned long long ffma2(unsigned long long a,
                                                    unsigned long long b,
                                                    unsigned long long c) {
    unsigned long long d;
    asm("fma.rn.f32x2 %0, %1, %2, %3;" : "=l"(d) : "l"(a), "l"(b), "l"(c));
    return d;
}
__device__ __forceinline__ float hsum2(unsigned long long v) {
    float lo, hi;
    asm("mov.b64 {%0, %1}, %2;" : "=f"(lo), "=f"(hi) : "l"(v));
    return lo + hi;
}
__device__ __forceinline__ float tanh_ap(float x) {
    float y;
    asm("tanh.approx.f32 %0, %1;" : "=f"(y) : "f"(x));
    return y;
}
__device__ __forceinline__ float sig_ap(float x) {
    return 0.5f * tanh_ap(0.5f * x) + 0.5f;
}
__device__ __forceinline__ uint32_t tf32r(float x) {
    uint32_t r;
    asm("cvt.rna.tf32.f32 %0, %1;" : "=r"(r) : "f"(x));
    return r;
}

// ---------------- profiling-slot shifters (no-op) ----------------
__global__ void k_pre1() {}
__global__ void k_pre2() {}

// ===========================================================================
// K1: fused embedding gather + input projection GEMM via tf32 mma.sync,
//   t-blocked (R12 form — proven).
// ===========================================================================
__global__ void __launch_bounds__(512) k_inproj(
    const int*   __restrict__ sent,
    const float* __restrict__ embed,
    const float* __restrict__ wih_f, const float* __restrict__ wih_b,
    const float* __restrict__ bih_f, const float* __restrict__ bhh_f,
    const float* __restrict__ bih_b, const float* __restrict__ bhh_b)
{
    extern __shared__ uint32_t smem_u32[];
    uint32_t* As = smem_u32;                 // [128][68]
    uint32_t* Bs = smem_u32 + 128 * 68;      // [2][64][68]
    __shared__ int words[2][64];

    const int tg    = blockIdx.x;
    const int ctile = blockIdx.y;
    const int d     = ctile >> 3;
    const int c0    = (ctile & 7) * 128;
    const int t0    = tg * 2;
    const int tid   = threadIdx.x;

    const float* __restrict__ wih = d ? wih_b : wih_f;
    const float* __restrict__ bih = d ? bih_b : bih_f;
    const float* __restrict__ bhh = d ? bhh_b : bhh_f;

    if (tid < 128) {
        int tt = tid >> 6, bb = tid & 63;
        words[tt][bb] = sent[bb * 512 + t0 + tt];
    }
    __syncthreads();

    const int w    = tid >> 5;
    const int lane = tid & 31;
    const int g    = lane >> 2;
    const int tg4  = lane & 3;
    const int cw   = (w & 7) * 16;
    const int bw   = (w >> 3) * 32;

    const int fra = tid >> 2;
    const int fq  = tid & 3;
    const int bt  = tid >> 8;
    const int frb = (tid >> 2) & 63;

    float acc[2][4][4];
    #pragma unroll
    for (int tt = 0; tt < 2; tt++)
        #pragma unroll
        for (int nt = 0; nt < 4; nt++)
            #pragma unroll
            for (int i = 0; i < 4; i++) acc[tt][nt][i] = 0.f;

    const float* __restrict__ wrow = wih + (size_t)(c0 + fra) * 300;
    const float* __restrict__ erow = embed + (size_t)words[bt][frb] * 300;

    for (int k0 = 0; k0 < 320; k0 += 64) {
        #pragma unroll
        for (int u = 0; u < 4; u++) {
            int q = fq + 4 * u;
            int k = k0 + q * 4;
            uint32_t va0 = 0, va1 = 0, va2 = 0, va3 = 0;
            uint32_t vb0 = 0, vb1 = 0, vb2 = 0, vb3 = 0;
            if (k < 300) {
                float4 av = *(const float4*)&wrow[k];
                float4 bv = *(const float4*)&erow[k];
                va0 = tf32r(av.x); va1 = tf32r(av.y);
                va2 = tf32r(av.z); va3 = tf32r(av.w);
                vb0 = tf32r(bv.x); vb1 = tf32r(bv.y);
                vb2 = tf32r(bv.z); vb3 = tf32r(bv.w);
            }
            *(uint4*)&As[fra * 68 + q * 4] = make_uint4(va0, va1, va2, va3);
            *(uint4*)&Bs[(bt * 64 + frb) * 68 + q * 4] =
                make_uint4(vb0, vb1, vb2, vb3);
        }
        __syncthreads();

        #pragma unroll
        for (int s = 0; s < 16; s++) {
            const int kk = s * 4 + tg4;
            uint32_t a0 = As[(cw + g) * 68 + kk];
            uint32_t a1 = As[(cw + g + 8) * 68 + kk];
            #pragma unroll
            for (int tt = 0; tt < 2; tt++) {
                #pragma unroll
                for (int nt = 0; nt < 4; nt++) {
                    uint32_t b0 = Bs[(tt * 64 + bw + nt * 8 + g) * 68 + kk];
                    asm volatile(
                        "mma.sync.aligned.m16n8k4.row.col.f32.tf32.tf32.f32 "
                        "{%0,%1,%2,%3}, {%4,%5}, {%6}, {%0,%1,%2,%3};"
                        : "+f"(acc[tt][nt][0]), "+f"(acc[tt][nt][1]),
                          "+f"(acc[tt][nt][2]), "+f"(acc[tt][nt][3])
                        : "r"(a0), "r"(a1), "r"(b0));
                }
            }
        }
        __syncthreads();
    }

    const int cA = c0 + cw + g;
    const int cB = cA + 8;
    const float biasA = bih[cA] + bhh[cA];
    const float biasB = bih[cB] + bhh[cB];
    #pragma unroll
    for (int tt = 0; tt < 2; tt++) {
        const size_t obase = ((size_t)d * 512 + t0 + tt) * 65536;
        #pragma unroll
        for (int nt = 0; nt < 4; nt++) {
            const int bcol = bw + nt * 8 + 2 * tg4;
            float2 vA = make_float2(acc[tt][nt][0] + biasA,
                                    acc[tt][nt][1] + biasA);
            float2 vB = make_float2(acc[tt][nt][2] + biasB,
                                    acc[tt][nt][3] + biasB);
            *(float2*)&g_xp[obase + (size_t)cA * 64 + bcol] = vA;
            *(float2*)&g_xp[obase + (size_t)cB * 64 + bcol] = vB;
        }
    }
}

// ===========================================================================
// K2: persistent bidirectional LSTM recurrence — R5 step-loop structure,
//   halved CTA population: 64 CTAs (32/dir), 512 thr; CTA m owns cols
//   [8m, 8m+8). Same per-thread work, same 4-chunk cp.async staging, same
//   single-poller monotone barrier (target 32*t). Fewer participants ->
//   smaller max-of-N skew tail + lower poll/release fan-in.
//   Dynamic smem: wint 32KB + hstage 64KB = 96KB.
// ===========================================================================
__global__ void __launch_bounds__(512, 1) k_rec(
    const float* __restrict__ whh_f, const float* __restrict__ whh_b)
{
    extern __shared__ float dsm[];
    float* wint   = dsm;            // 8192 floats (32KB): f4[(hcl*4+g)*64+jq]
    float* hstage = dsm + 8192;     // 16384 floats (64KB): f4[jq*64+b]

    const int bx  = blockIdx.x;
    const int d   = bx >> 5;        // direction (0..1), 32 CTAs each
    const int m   = bx & 31;
    const int hc0 = m * 8;
    const int tid = threadIdx.x;
    const int hcl = tid >> 6;       // 0..7 local column
    const int b   = tid & 63;
    const float* __restrict__ whh = d ? whh_b : whh_f;

    // weight quads: wint f4 row (hcl*4+g), col jq  -> whh[(g*256+hc0+hcl)][4jq..]
    for (int q = tid; q < 2048; q += 512) {
        int row = q >> 6, jq = q & 63;
        int g = row & 3, hl = row >> 2;     // hl 0..7
        *(float4*)&wint[q * 4] =
            *(const float4*)&whh[(size_t)(g * 256 + hc0 + hl) * 256 + 4 * jq];
    }
    __syncthreads();

    const ulonglong2* __restrict__ w2 = (const ulonglong2*)wint;
    const float4* __restrict__ hst4 = (const float4*)hstage;
    const unsigned hstage_s = (unsigned)__cvta_generic_to_shared(hstage);
    const int wr0 = (hcl * 4 + 0) * 64;
    const int wr1 = (hcl * 4 + 1) * 64;
    const int wr2 = (hcl * 4 + 2) * 64;
    const int wr3 = (hcl * 4 + 3) * 64;

    int* __restrict__ cbase = &g_cnt[d * 512];

    // store location: column c = hc0+hcl lives in quad jq = c>>2, slot c&3
    const int st_jq = (hc0 + hcl) >> 2;
    const int st_k  = (hc0 + hcl) & 3;

    float cstate = 0.f;

    const int tt_first = d ? 511 : 0;
    size_t xb = ((size_t)d * 512 + tt_first) * 65536;
    float xi = g_xp[xb + (size_t)(hc0 + hcl) * 64 + b];
    float xf = g_xp[xb + (size_t)(256 + hc0 + hcl) * 64 + b];
    float xg = g_xp[xb + (size_t)(512 + hc0 + hcl) * 64 + b];
    float xo = g_xp[xb + (size_t)(768 + hc0 + hcl) * 64 + b];

    for (int t = 0; t < 512; t++) {
        const int tt = d ? (511 - t) : t;

        float ai, af, ag, ao;

        if (t > 0) {
            // wait for all 32 CTAs of this direction to finish step t-1
            if (tid == 0) {
                const int target = 32 * t;
                int s;
                do {
                    s = 0;
                    #pragma unroll
                    for (int i = 0; i < 8; i++) {
                        int v;
                        asm volatile("ld.relaxed.gpu.global.s32 %0, [%1];"
                                     : "=r"(v) : "l"(cbase + i * 32));
                        s += v;
                    }
                } while (s < target);
                int dummy;
                asm volatile("ld.acquire.gpu.global.s32 %0, [%1];"
                             : "=r"(dummy) : "l"(cbase) : "memory");
            }
            __syncthreads();

            const int hp = d ? (tt + 1) : (tt - 1);
            const float4* __restrict__ srcF4 =
                (const float4*)&g_hP[((size_t)hp * 2 + d) * 16384];

            #pragma unroll
            for (int q = 0; q < 4; q++) {
                #pragma unroll
                for (int r = 0; r < 2; r++) {
                    int f4i = q * 1024 + r * 512 + tid;
                    unsigned sa = hstage_s + (unsigned)f4i * 16u;
                    asm volatile("cp.async.cg.shared.global [%0], [%1], 16;"
                                 :: "r"(sa), "l"(srcF4 + f4i) : "memory");
                }
                asm volatile("cp.async.commit_group;" ::: "memory");
            }

            unsigned long long a0 = 0, a1 = 0, a2 = 0, a3 = 0;

            #define GEMM_CHUNK(Q, W)                                            \
                asm volatile("cp.async.wait_group %0;" :: "n"(W) : "memory");   \
                __syncthreads();                                                \
                _Pragma("unroll")                                               \
                for (int jq = (Q) * 16; jq < (Q) * 16 + 16; jq++) {             \
                    ulonglong2 h2 = *(const ulonglong2*)&hst4[jq * 64 + b];     \
                    ulonglong2 q0 = w2[wr0 + jq];                               \
                    ulonglong2 q1 = w2[wr1 + jq];                               \
                    ulonglong2 q2 = w2[wr2 + jq];                               \
                    ulonglong2 q3 = w2[wr3 + jq];                               \
                    a0 = ffma2(q0.x, h2.x, a0); a0 = ffma2(q0.y, h2.y, a0);     \
                    a1 = ffma2(q1.x, h2.x, a1); a1 = ffma2(q1.y, h2.y, a1);     \
                    a2 = ffma2(q2.x, h2.x, a2); a2 = ffma2(q2.y, h2.y, a2);     \
                    a3 = ffma2(q3.x, h2.x, a3); a3 = ffma2(q3.y, h2.y, a3);     \
                }
            GEMM_CHUNK(0, 3)
            GEMM_CHUNK(1, 2)
            GEMM_CHUNK(2, 1)
            GEMM_CHUNK(3, 0)
            #undef GEMM_CHUNK

            ai = hsum2(a0) + xi; af = hsum2(a1) + xf;
            ag = hsum2(a2) + xg; ao = hsum2(a3) + xo;
        } else {
            ai = xi; af = xf; ag = xg; ao = xo;
        }

        const float si = sig_ap(ai);
        const float sf = sig_ap(af);
        const float so = sig_ap(ao);
        cstate = sf * cstate + si * tanh_ap(ag);
        const float hval = so * tanh_ap(cstate);

        // quad-interleaved store: [tt][d][st_jq][b][st_k]
        g_hP[((size_t)tt * 2 + d) * 16384 + (size_t)(st_jq * 64 + b) * 4 + st_k]
            = hval;

        // prefetch next step's x gates
        if (t < 511) {
            const int tn = d ? (510 - t) : (t + 1);
            const size_t xnb = ((size_t)d * 512 + tn) * 65536;
            xi = g_xp[xnb + (size_t)(hc0 + hcl) * 64 + b];
            xf = g_xp[xnb + (size_t)(256 + hc0 + hcl) * 64 + b];
            xg = g_xp[xnb + (size_t)(512 + hc0 + hcl) * 64 + b];
            xo = g_xp[xnb + (size_t)(768 + hc0 + hcl) * 64 + b];
        }

        // arrival: fire-and-forget release add on this CTA's sub-counter
        __syncthreads();
        if (tid == 0) {
            asm volatile("red.release.gpu.global.add.s32 [%0], 1;"
                         :: "l"(cbase + (m & 7) * 32) : "memory");
        }
    }
}

// ===========================================================================
// K3: emissions from g_hP + barrier-counter reset for next graph replay.
// ===========================================================================
__global__ void __launch_bounds__(256) k_emis(
    const float* __restrict__ w_out, const float* __restrict__ b_out)
{
    if (blockIdx.x == 0 && threadIdx.x < 16)
        g_cnt[(threadIdx.x >> 3) * 512 + (threadIdx.x & 7) * 32] = 0;

    __shared__ float w_s[9 * 512];
    __shared__ float red[4][64][10];

    const int t = blockIdx.x, tid = threadIdx.x;
    for (int i = tid; i < 9 * 512; i += 256) w_s[i] = w_out[i];
    __syncthreads();

    const int b = tid & 63, seg = tid >> 6;
    const int d = seg >> 1, jq0 = (seg & 1) * 32;
    float acc[9] = {};
    const float4* __restrict__ hp4 =
        (const float4*)&g_hP[((size_t)t * 2 + d) * 16384];
    for (int jq = jq0; jq < jq0 + 32; jq++) {
        float4 h4 = hp4[jq * 64 + b];
        const int cb = d * 256 + 4 * jq;
        #pragma unroll
        for (int tau = 0; tau < 9; tau++) {
            acc[tau] += h4.x * w_s[tau * 512 + cb + 0]
                      + h4.y * w_s[tau * 512 + cb + 1]
                      + h4.z * w_s[tau * 512 + cb + 2]
                      + h4.w * w_s[tau * 512 + cb + 3];
        }
    }
    #pragma unroll
    for (int tau = 0; tau < 9; tau++) red[seg][b][tau] = acc[tau];
    __syncthreads();
    if (seg == 0) {
        #pragma unroll
        for (int tau = 0; tau < 9; tau++) {
            float v = red[0][b][tau] + red[1][b][tau] + red[2][b][tau] +
                      red[3][b][tau] + b_out[tau];
            g_emis[(size_t)t * 576 + b * 9 + tau] = v;
        }
    }
}

// ===========================================================================
// K4: CRF gold score + forward algorithm (logZ). grid 64 (b), 1 warp each.
//   Depth-4 register-ring prefetch of em/mask hides L2 latency.
// ===========================================================================
__global__ void k_crf(
    const int*   __restrict__ tags, const int* __restrict__ mask,
    const float* __restrict__ start_trans, const float* __restrict__ end_trans,
    const float* __restrict__ trans)
{
    const int b = blockIdx.x, lane = threadIdx.x;

    float sc = 0.f; int cnt = 0;
    for (int t = lane; t < 512; t += 32) {
        int mk = mask[b * 512 + t];
        cnt += mk;
        if (t >= 1 && mk) {
            int tp = tags[b * 512 + t - 1];
            int tc = tags[b * 512 + t];
            sc += trans[tp * 9 + tc] + g_emis[(size_t)t * 576 + b * 9 + tc];
        }
    }
    #pragma unroll
    for (int o = 16; o > 0; o >>= 1) {
        sc  += __shfl_down_sync(0xffffffffu, sc, o);
        cnt += __shfl_down_sync(0xffffffffu, cnt, o);
    }
    int len = __shfl_sync(0xffffffffu, cnt, 0);
    float score = 0.f;
    if (lane == 0) {
        int t0 = tags[b * 512];
        score = sc + start_trans[t0] + g_emis[b * 9 + t0];
        int tl = tags[b * 512 + len - 1];
        score += end_trans[tl];
    }

    float logZ = 0.f;
    if (lane < 9) {
        const int j = lane;
        float E[9];
        #pragma unroll
        for (int i = 0; i < 9; i++) E[i] = __expf(trans[i * 9 + j]);

        float a = start_trans[j] + g_emis[b * 9 + j];
        float a0 = __shfl_sync(0x1ffu, a, 0);
        float base = a0;
        a -= a0;

        float em_r[4]; int mk_r[4];
        #pragma unroll
        for (int i = 0; i < 4; i++) {
            int tt = 1 + i;
            em_r[i] = (tt < 512) ? g_emis[(size_t)tt * 576 + b * 9 + j] : 0.f;
            mk_r[i] = (tt < 512) ? mask[b * 512 + tt] : 0;
        }

        for (int t = 1; t < 512; t++) {
            const int k = (t - 1) & 3;
            const int   mk = mk_r[k];
            const float em = em_r[k];
            if (!mk) break;
            const int tp = t + 4;
            if (tp < 512) {
                em_r[k] = g_emis[(size_t)tp * 576 + b * 9 + j];
                mk_r[k] = mask[b * 512 + tp];
            } else {
                mk_r[k] = 0;
            }
            float ea = __expf(a);
            float s0 = 0.f, s1 = 0.f, s2 = 0.f;
            #pragma unroll
            for (int i = 0; i < 9; i += 3) {
                float e0 = __shfl_sync(0x1ffu, ea, i);
                float e1 = __shfl_sync(0x1ffu, ea, i + 1);
                float e2 = __shfl_sync(0x1ffu, ea, i + 2);
                s0 += e0 * E[i];
                s1 += e1 * E[i + 1];
                s2 += e2 * E[i + 2];
            }
            float u = __logf(s0 + s1 + s2) + em;
            float u0 = __shfl_sync(0x1ffu, u, 0);
            base += u0;
            a = u - u0;
        }
        float z = a + end_trans[j];
        float ez = __expf(z);
        float s = 0.f;
        #pragma unroll
        for (int i = 0; i < 9; i++) s += __shfl_sync(0x1ffu, ez, i);
        logZ = base + __logf(s);
    }
    if (lane == 0) g_llh[b] = score - logZ;
}

// ===========================================================================
// K5: final deterministic reduction  out = -mean(llh)
// ===========================================================================
__global__ void k_final(float* __restrict__ out)
{
    __shared__ float s[64];
    const int tid = threadIdx.x;
    s[tid] = g_llh[tid];
    __syncthreads();
    if (tid == 0) {
        float acc = 0.f;
        for (int i = 0; i < 64; i++) acc += s[i];
        out[0] = -acc / 64.f;
    }
}

// ===========================================================================
extern "C" void kernel_launch(void* const* d_in, const int* in_sizes, int n_in,
                              void* d_out, int out_size)
{
    const bool dictOrder = (in_sizes[2] == 15000000);
    const int ie = dictOrder ? 2 : 3;
    const int im = dictOrder ? 16 : 2;

    const int*   sent    = (const int*)  d_in[0];
    const int*   tags    = (const int*)  d_in[1];
    const float* embed   = (const float*)d_in[ie + 0];
    const float* wih_f   = (const float*)d_in[ie + 1];
    const float* whh_f   = (const float*)d_in[ie + 2];
    const float* bih_f   = (const float*)d_in[ie + 3];
    const float* bhh_f   = (const float*)d_in[ie + 4];
    const float* wih_b   = (const float*)d_in[ie + 5];
    const float* whh_b   = (const float*)d_in[ie + 6];
    const float* bih_b   = (const float*)d_in[ie + 7];
    const float* bhh_b   = (const float*)d_in[ie + 8];
    const float* w_out   = (const float*)d_in[ie + 9];
    const float* b_out   = (const float*)d_in[ie + 10];
    const float* s_tr    = (const float*)d_in[ie + 11];
    const float* e_tr    = (const float*)d_in[ie + 12];
    const float* trans   = (const float*)d_in[ie + 13];
    const int*   mask    = (const int*)  d_in[im];
    float*       out     = (float*)d_out;

    cudaFuncSetAttribute(k_rec, cudaFuncAttributeMaxDynamicSharedMemorySize, 98304);
    cudaFuncSetAttribute(k_inproj, cudaFuncAttributeMaxDynamicSharedMemorySize, 69632);

    // shift the ncu -s/-c profiled slot onto k_rec
    k_pre1<<<1, 32>>>();
    k_pre2<<<1, 32>>>();

    dim3 g1(256, 16);
    k_inproj<<<g1, 512, 69632>>>(sent, embed, wih_f, wih_b, bih_f, bhh_f,
                                 bih_b, bhh_b);
    k_rec<<<64, 512, 98304>>>(whh_f, whh_b);
    k_emis<<<512, 256>>>(w_out, b_out);
    k_crf<<<64, 32>>>(tags, mask, s_tr, e_tr, trans);
    k_final<<<1, 64>>>(out);
}

// round 15
// speedup vs baseline: 1.4503x; 1.4503x over previous
#include <cuda_runtime.h>
#include <math.h>
#include <stdint.h>

// ---------------- device scratch ----------------
__device__ float g_xp[(size_t)2 * 512 * 1024 * 64];   // [dir][t][gate_row 0..1023][b]
__device__ float g_hP[(size_t)512 * 2 * 64 * 64 * 4]; // [t][d][jq][b][4]  (64MB)
__device__ float g_emis[(size_t)512 * 64 * 9];        // [t][b][tau]
__device__ float g_llh[64];
__device__ int   g_cnt[1024];                         // sub-counters: [d*512 + sub*32]

// ---------------- packed f32x2 helpers (Blackwell FFMA2) ----------------
__device__ __forceinline__ unsigned long long ffma2(unsigned long long a,
                                                    unsigned long long b,
                                                    unsigned long long c) {
    unsigned long long d;
    asm("fma.rn.f32x2 %0, %1, %2, %3;" : "=l"(d) : "l"(a), "l"(b), "l"(c));
    return d;
}
__device__ __forceinline__ float hsum2(unsigned long long v) {
    float lo, hi;
    asm("mov.b64 {%0, %1}, %2;" : "=f"(lo), "=f"(hi) : "l"(v));
    return lo + hi;
}
__device__ __forceinline__ float tanh_ap(float x) {
    float y;
    asm("tanh.approx.f32 %0, %1;" : "=f"(y) : "f"(x));
    return y;
}
__device__ __forceinline__ float sig_ap(float x) {
    return 0.5f * tanh_ap(0.5f * x) + 0.5f;
}
__device__ __forceinline__ uint32_t tf32r(float x) {
    uint32_t r;
    asm("cvt.rna.tf32.f32 %0, %1;" : "=r"(r) : "f"(x));
    return r;
}

// ---------------- profiling-slot shifters (no-op) ----------------
__global__ void k_pre1() {}
__global__ void k_pre2() {}

// ===========================================================================
// K1: fused embedding gather + input projection GEMM via tf32 mma.sync,
//   t-blocked x4: block = 128 c x 64 b x 4 t, grid (tg=128, ctile=16).
//   A (wih 128xK) loaded once per 4 t; B per-t tiles in smem.
//   Dynamic smem: As 128x68 + Bs 4x64x68 u32 = 102KB.
// ===========================================================================
__global__ void __launch_bounds__(512) k_inproj(
    const int*   __restrict__ sent,
    const float* __restrict__ embed,
    const float* __restrict__ wih_f, const float* __restrict__ wih_b,
    const float* __restrict__ bih_f, const float* __restrict__ bhh_f,
    const float* __restrict__ bih_b, const float* __restrict__ bhh_b)
{
    extern __shared__ uint32_t smem_u32[];
    uint32_t* As = smem_u32;                 // [128][68]
    uint32_t* Bs = smem_u32 + 128 * 68;      // [4][64][68]
    __shared__ int words[4][64];

    const int tg    = blockIdx.x;
    const int ctile = blockIdx.y;
    const int d     = ctile >> 3;
    const int c0    = (ctile & 7) * 128;
    const int t0    = tg * 4;
    const int tid   = threadIdx.x;

    const float* __restrict__ wih = d ? wih_b : wih_f;
    const float* __restrict__ bih = d ? bih_b : bih_f;
    const float* __restrict__ bhh = d ? bhh_b : bhh_f;

    if (tid < 256) {
        int tt = tid >> 6, bb = tid & 63;
        words[tt][bb] = sent[bb * 512 + t0 + tt];
    }
    __syncthreads();

    const int w    = tid >> 5;       // 0..15
    const int lane = tid & 31;
    const int g    = lane >> 2;      // 0..7
    const int tg4  = lane & 3;       // 0..3
    const int cw   = (w & 7) * 16;   // 8 c-warps x 16 = 128
    const int bw   = (w >> 3) * 32;  // 2 b-warps x 32 = 64

    // A fill: rows 0..127, 4 quads per thread
    const int fra = tid >> 2;        // 0..127
    const int fqa = tid & 3;         // 0..3
    // B fill: 4 tiles x 64 rows; 8 quads per thread
    const int bt  = tid >> 7;        // 0..3
    const int frb = (tid >> 1) & 63; // 0..63
    const int fqb = tid & 1;         // 0..1

    float acc[4][4][4];
    #pragma unroll
    for (int tt = 0; tt < 4; tt++)
        #pragma unroll
        for (int nt = 0; nt < 4; nt++)
            #pragma unroll
            for (int i = 0; i < 4; i++) acc[tt][nt][i] = 0.f;

    const float* __restrict__ wrow = wih + (size_t)(c0 + fra) * 300;
    const float* __restrict__ erow = embed + (size_t)words[bt][frb] * 300;

    for (int k0 = 0; k0 < 320; k0 += 64) {
        // ---- A fill (tf32-rounded); zero past k=300 ----
        #pragma unroll
        for (int u = 0; u < 4; u++) {
            int q = fqa + 4 * u;           // 0..15
            int k = k0 + q * 4;
            uint32_t v0 = 0, v1 = 0, v2 = 0, v3 = 0;
            if (k < 300) {
                float4 av = *(const float4*)&wrow[k];
                v0 = tf32r(av.x); v1 = tf32r(av.y);
                v2 = tf32r(av.z); v3 = tf32r(av.w);
            }
            *(uint4*)&As[fra * 68 + q * 4] = make_uint4(v0, v1, v2, v3);
        }
        // ---- B fill ----
        #pragma unroll
        for (int u = 0; u < 8; u++) {
            int q = fqb + 2 * u;           // 0..15
            int k = k0 + q * 4;
            uint32_t v0 = 0, v1 = 0, v2 = 0, v3 = 0;
            if (k < 300) {
                float4 bv = *(const float4*)&erow[k];
                v0 = tf32r(bv.x); v1 = tf32r(bv.y);
                v2 = tf32r(bv.z); v3 = tf32r(bv.w);
            }
            *(uint4*)&Bs[(bt * 64 + frb) * 68 + q * 4] = make_uint4(v0, v1, v2, v3);
        }
        __syncthreads();

        // ---- 16 k-steps of m16n8k4; all 4 t's share A fragments ----
        #pragma unroll
        for (int s = 0; s < 16; s++) {
            const int kk = s * 4 + tg4;
            uint32_t a0 = As[(cw + g) * 68 + kk];
            uint32_t a1 = As[(cw + g + 8) * 68 + kk];
            #pragma unroll
            for (int tt = 0; tt < 4; tt++) {
                #pragma unroll
                for (int nt = 0; nt < 4; nt++) {
                    uint32_t b0 = Bs[(tt * 64 + bw + nt * 8 + g) * 68 + kk];
                    asm volatile(
                        "mma.sync.aligned.m16n8k4.row.col.f32.tf32.tf32.f32 "
                        "{%0,%1,%2,%3}, {%4,%5}, {%6}, {%0,%1,%2,%3};"
                        : "+f"(acc[tt][nt][0]), "+f"(acc[tt][nt][1]),
                          "+f"(acc[tt][nt][2]), "+f"(acc[tt][nt][3])
                        : "r"(a0), "r"(a1), "r"(b0));
                }
            }
        }
        __syncthreads();
    }

    // ---- epilogue: bias + store ----
    const int cA = c0 + cw + g;
    const int cB = cA + 8;
    const float biasA = bih[cA] + bhh[cA];
    const float biasB = bih[cB] + bhh[cB];
    #pragma unroll
    for (int tt = 0; tt < 4; tt++) {
        const size_t obase = ((size_t)d * 512 + t0 + tt) * 65536;
        #pragma unroll
        for (int nt = 0; nt < 4; nt++) {
            const int bcol = bw + nt * 8 + 2 * tg4;
            float2 vA = make_float2(acc[tt][nt][0] + biasA,
                                    acc[tt][nt][1] + biasA);
            float2 vB = make_float2(acc[tt][nt][2] + biasB,
                                    acc[tt][nt][3] + biasB);
            *(float2*)&g_xp[obase + (size_t)cA * 64 + bcol] = vA;
            *(float2*)&g_xp[obase + (size_t)cB * 64 + bcol] = vB;
        }
    }
}

// ===========================================================================
// K2: persistent bidirectional LSTM recurrence — EXACT R12/R5 form
//   (measured best across 7 variants; frozen). 128 CTAs (64/dir), 256 thr.
// ===========================================================================
__global__ void __launch_bounds__(256, 1) k_rec(
    const float* __restrict__ whh_f, const float* __restrict__ whh_b)
{
    extern __shared__ float dsm[];
    float* wint   = dsm;            // 4096 floats (16KB): f4[(hcl*4+g)*64+jq]
    float* hstage = dsm + 4096;     // 16384 floats (64KB): f4[jq*64+b]

    const int bx  = blockIdx.x;
    const int d   = bx >> 6;
    const int m   = bx & 63;
    const int hc0 = m * 4;
    const int tid = threadIdx.x;
    const int hcl = tid >> 6;       // 0..3
    const int b   = tid & 63;
    const float* __restrict__ whh = d ? whh_b : whh_f;

    for (int q = tid; q < 1024; q += 256) {
        int row = q >> 6, jq = q & 63;
        int g = row & 3, hl = row >> 2;
        *(float4*)&wint[q * 4] =
            *(const float4*)&whh[(size_t)(g * 256 + hc0 + hl) * 256 + 4 * jq];
    }
    __syncthreads();

    const ulonglong2* __restrict__ w2 = (const ulonglong2*)wint;
    const float4* __restrict__ hst4 = (const float4*)hstage;
    const unsigned hstage_s = (unsigned)__cvta_generic_to_shared(hstage);
    const int wr0 = (hcl * 4 + 0) * 64;
    const int wr1 = (hcl * 4 + 1) * 64;
    const int wr2 = (hcl * 4 + 2) * 64;
    const int wr3 = (hcl * 4 + 3) * 64;

    int* __restrict__ cbase = &g_cnt[d * 512];

    float cstate = 0.f;

    const int tt_first = d ? 511 : 0;
    size_t xb = ((size_t)d * 512 + tt_first) * 65536;
    float xi = g_xp[xb + (size_t)(hc0 + hcl) * 64 + b];
    float xf = g_xp[xb + (size_t)(256 + hc0 + hcl) * 64 + b];
    float xg = g_xp[xb + (size_t)(512 + hc0 + hcl) * 64 + b];
    float xo = g_xp[xb + (size_t)(768 + hc0 + hcl) * 64 + b];

    for (int t = 0; t < 512; t++) {
        const int tt = d ? (511 - t) : t;

        float ai, af, ag, ao;

        if (t > 0) {
            if (tid == 0) {
                const int target = 64 * t;
                int s;
                do {
                    s = 0;
                    #pragma unroll
                    for (int i = 0; i < 8; i++) {
                        int v;
                        asm volatile("ld.relaxed.gpu.global.s32 %0, [%1];"
                                     : "=r"(v) : "l"(cbase + i * 32));
                        s += v;
                    }
                } while (s < target);
                int dummy;
                asm volatile("ld.acquire.gpu.global.s32 %0, [%1];"
                             : "=r"(dummy) : "l"(cbase) : "memory");
            }
            __syncthreads();

            const int hp = d ? (tt + 1) : (tt - 1);
            const float4* __restrict__ srcF4 =
                (const float4*)&g_hP[((size_t)hp * 2 + d) * 16384];

            #pragma unroll
            for (int q = 0; q < 4; q++) {
                #pragma unroll
                for (int r = 0; r < 4; r++) {
                    int f4i = q * 1024 + r * 256 + tid;
                    unsigned sa = hstage_s + (unsigned)f4i * 16u;
                    asm volatile("cp.async.cg.shared.global [%0], [%1], 16;"
                                 :: "r"(sa), "l"(srcF4 + f4i) : "memory");
                }
                asm volatile("cp.async.commit_group;" ::: "memory");
            }

            unsigned long long a0 = 0, a1 = 0, a2 = 0, a3 = 0;

            #define GEMM_CHUNK(Q, W)                                            \
                asm volatile("cp.async.wait_group %0;" :: "n"(W) : "memory");   \
                __syncthreads();                                                \
                _Pragma("unroll")                                               \
                for (int jq = (Q) * 16; jq < (Q) * 16 + 16; jq++) {             \
                    ulonglong2 h2 = *(const ulonglong2*)&hst4[jq * 64 + b];     \
                    ulonglong2 q0 = w2[wr0 + jq];                               \
                    ulonglong2 q1 = w2[wr1 + jq];                               \
                    ulonglong2 q2 = w2[wr2 + jq];                               \
                    ulonglong2 q3 = w2[wr3 + jq];                               \
                    a0 = ffma2(q0.x, h2.x, a0); a0 = ffma2(q0.y, h2.y, a0);     \
                    a1 = ffma2(q1.x, h2.x, a1); a1 = ffma2(q1.y, h2.y, a1);     \
                    a2 = ffma2(q2.x, h2.x, a2); a2 = ffma2(q2.y, h2.y, a2);     \
                    a3 = ffma2(q3.x, h2.x, a3); a3 = ffma2(q3.y, h2.y, a3);     \
                }
            GEMM_CHUNK(0, 3)
            GEMM_CHUNK(1, 2)
            GEMM_CHUNK(2, 1)
            GEMM_CHUNK(3, 0)
            #undef GEMM_CHUNK

            ai = hsum2(a0) + xi; af = hsum2(a1) + xf;
            ag = hsum2(a2) + xg; ao = hsum2(a3) + xo;
        } else {
            ai = xi; af = xf; ag = xg; ao = xo;
        }

        const float si = sig_ap(ai);
        const float sf = sig_ap(af);
        const float so = sig_ap(ao);
        cstate = sf * cstate + si * tanh_ap(ag);
        const float hval = so * tanh_ap(cstate);

        g_hP[((size_t)tt * 2 + d) * 16384 + (size_t)(m * 64 + b) * 4 + hcl] = hval;

        if (t < 511) {
            const int tn = d ? (510 - t) : (t + 1);
            const size_t xnb = ((size_t)d * 512 + tn) * 65536;
            xi = g_xp[xnb + (size_t)(hc0 + hcl) * 64 + b];
            xf = g_xp[xnb + (size_t)(256 + hc0 + hcl) * 64 + b];
            xg = g_xp[xnb + (size_t)(512 + hc0 + hcl) * 64 + b];
            xo = g_xp[xnb + (size_t)(768 + hc0 + hcl) * 64 + b];
        }

        __syncthreads();
        if (tid == 0) {
            asm volatile("red.release.gpu.global.add.s32 [%0], 1;"
                         :: "l"(cbase + (m & 7) * 32) : "memory");
        }
    }
}

// ===========================================================================
// K3: emissions from g_hP + barrier-counter reset for next graph replay.
// ===========================================================================
__global__ void __launch_bounds__(256) k_emis(
    const float* __restrict__ w_out, const float* __restrict__ b_out)
{
    if (blockIdx.x == 0 && threadIdx.x < 16)
        g_cnt[(threadIdx.x >> 3) * 512 + (threadIdx.x & 7) * 32] = 0;

    __shared__ float w_s[9 * 512];
    __shared__ float red[4][64][10];

    const int t = blockIdx.x, tid = threadIdx.x;
    for (int i = tid; i < 9 * 512; i += 256) w_s[i] = w_out[i];
    __syncthreads();

    const int b = tid & 63, seg = tid >> 6;
    const int d = seg >> 1, jq0 = (seg & 1) * 32;
    float acc[9] = {};
    const float4* __restrict__ hp4 =
        (const float4*)&g_hP[((size_t)t * 2 + d) * 16384];
    for (int jq = jq0; jq < jq0 + 32; jq++) {
        float4 h4 = hp4[jq * 64 + b];
        const int cb = d * 256 + 4 * jq;
        #pragma unroll
        for (int tau = 0; tau < 9; tau++) {
            acc[tau] += h4.x * w_s[tau * 512 + cb + 0]
                      + h4.y * w_s[tau * 512 + cb + 1]
                      + h4.z * w_s[tau * 512 + cb + 2]
                      + h4.w * w_s[tau * 512 + cb + 3];
        }
    }
    #pragma unroll
    for (int tau = 0; tau < 9; tau++) red[seg][b][tau] = acc[tau];
    __syncthreads();
    if (seg == 0) {
        #pragma unroll
        for (int tau = 0; tau < 9; tau++) {
            float v = red[0][b][tau] + red[1][b][tau] + red[2][b][tau] +
                      red[3][b][tau] + b_out[tau];
            g_emis[(size_t)t * 576 + b * 9 + tau] = v;
        }
    }
}

// ===========================================================================
// K4: CRF gold score + forward algorithm (logZ). grid 64 (b), 1 warp each.
//   Depth-4 register-ring prefetch of em/mask hides L2 latency.
// ===========================================================================
__global__ void k_crf(
    const int*   __restrict__ tags, const int* __restrict__ mask,
    const float* __restrict__ start_trans, const float* __restrict__ end_trans,
    const float* __restrict__ trans)
{
    const int b = blockIdx.x, lane = threadIdx.x;

    float sc = 0.f; int cnt = 0;
    for (int t = lane; t < 512; t += 32) {
        int mk = mask[b * 512 + t];
        cnt += mk;
        if (t >= 1 && mk) {
            int tp = tags[b * 512 + t - 1];
            int tc = tags[b * 512 + t];
            sc += trans[tp * 9 + tc] + g_emis[(size_t)t * 576 + b * 9 + tc];
        }
    }
    #pragma unroll
    for (int o = 16; o > 0; o >>= 1) {
        sc  += __shfl_down_sync(0xffffffffu, sc, o);
        cnt += __shfl_down_sync(0xffffffffu, cnt, o);
    }
    int len = __shfl_sync(0xffffffffu, cnt, 0);
    float score = 0.f;
    if (lane == 0) {
        int t0 = tags[b * 512];
        score = sc + start_trans[t0] + g_emis[b * 9 + t0];
        int tl = tags[b * 512 + len - 1];
        score += end_trans[tl];
    }

    float logZ = 0.f;
    if (lane < 9) {
        const int j = lane;
        float E[9];
        #pragma unroll
        for (int i = 0; i < 9; i++) E[i] = __expf(trans[i * 9 + j]);

        float a = start_trans[j] + g_emis[b * 9 + j];
        float a0 = __shfl_sync(0x1ffu, a, 0);
        float base = a0;
        a -= a0;

        float em_r[4]; int mk_r[4];
        #pragma unroll
        for (int i = 0; i < 4; i++) {
            int tt = 1 + i;
            em_r[i] = (tt < 512) ? g_emis[(size_t)tt * 576 + b * 9 + j] : 0.f;
            mk_r[i] = (tt < 512) ? mask[b * 512 + tt] : 0;
        }

        for (int t = 1; t < 512; t++) {
            const int k = (t - 1) & 3;
            const int   mk = mk_r[k];
            const float em = em_r[k];
            if (!mk) break;
            const int tp = t + 4;
            if (tp < 512) {
                em_r[k] = g_emis[(size_t)tp * 576 + b * 9 + j];
                mk_r[k] = mask[b * 512 + tp];
            } else {
                mk_r[k] = 0;
            }
            float ea = __expf(a);
            float s0 = 0.f, s1 = 0.f, s2 = 0.f;
            #pragma unroll
            for (int i = 0; i < 9; i += 3) {
                float e0 = __shfl_sync(0x1ffu, ea, i);
                float e1 = __shfl_sync(0x1ffu, ea, i + 1);
                float e2 = __shfl_sync(0x1ffu, ea, i + 2);
                s0 += e0 * E[i];
                s1 += e1 * E[i + 1];
                s2 += e2 * E[i + 2];
            }
            float u = __logf(s0 + s1 + s2) + em;
            float u0 = __shfl_sync(0x1ffu, u, 0);
            base += u0;
            a = u - u0;
        }
        float z = a + end_trans[j];
        float ez = __expf(z);
        float s = 0.f;
        #pragma unroll
        for (int i = 0; i < 9; i++) s += __shfl_sync(0x1ffu, ez, i);
        logZ = base + __logf(s);
    }
    if (lane == 0) g_llh[b] = score - logZ;
}

// ===========================================================================
// K5: final deterministic reduction  out = -mean(llh)
// ===========================================================================
__global__ void k_final(float* __restrict__ out)
{
    __shared__ float s[64];
    const int tid = threadIdx.x;
    s[tid] = g_llh[tid];
    __syncthreads();
    if (tid == 0) {
        float acc = 0.f;
        for (int i = 0; i < 64; i++) acc += s[i];
        out[0] = -acc / 64.f;
    }
}

// ===========================================================================
extern "C" void kernel_launch(void* const* d_in, const int* in_sizes, int n_in,
                              void* d_out, int out_size)
{
    const bool dictOrder = (in_sizes[2] == 15000000);
    const int ie = dictOrder ? 2 : 3;
    const int im = dictOrder ? 16 : 2;

    const int*   sent    = (const int*)  d_in[0];
    const int*   tags    = (const int*)  d_in[1];
    const float* embed   = (const float*)d_in[ie + 0];
    const float* wih_f   = (const float*)d_in[ie + 1];
    const float* whh_f   = (const float*)d_in[ie + 2];
    const float* bih_f   = (const float*)d_in[ie + 3];
    const float* bhh_f   = (const float*)d_in[ie + 4];
    const float* wih_b   = (const float*)d_in[ie + 5];
    const float* whh_b   = (const float*)d_in[ie + 6];
    const float* bih_b   = (const float*)d_in[ie + 7];
    const float* bhh_b   = (const float*)d_in[ie + 8];
    const float* w_out   = (const float*)d_in[ie + 9];
    const float* b_out   = (const float*)d_in[ie + 10];
    const float* s_tr    = (const float*)d_in[ie + 11];
    const float* e_tr    = (const float*)d_in[ie + 12];
    const float* trans   = (const float*)d_in[ie + 13];
    const int*   mask    = (const int*)  d_in[im];
    float*       out     = (float*)d_out;

    cudaFuncSetAttribute(k_rec, cudaFuncAttributeMaxDynamicSharedMemorySize, 81920);
    cudaFuncSetAttribute(k_inproj, cudaFuncAttributeMaxDynamicSharedMemorySize, 104448);

    // shift the ncu -s/-c profiled slot onto k_rec
    k_pre1<<<1, 32>>>();
    k_pre2<<<1, 32>>>();

    dim3 g1(128, 16);
    k_inproj<<<g1, 512, 104448>>>(sent, embed, wih_f, wih_b, bih_f, bhh_f,
                                  bih_b, bhh_b);
    k_rec<<<128, 256, 81920>>>(whh_f, whh_b);
    k_emis<<<512, 256>>>(w_out, b_out);
    k_crf<<<64, 32>>>(tags, mask, s_tr, e_tr, trans);
    k_final<<<1, 64>>>(out);
}

// round 16
// speedup vs baseline: 1.5027x; 1.0362x over previous
#include <cuda_runtime.h>
#include <math.h>
#include <stdint.h>

// ---------------- device scratch ----------------
__device__ float g_xp[(size_t)2 * 512 * 1024 * 64];   // [dir][t][gate_row 0..1023][b]
__device__ float g_hP[(size_t)512 * 2 * 64 * 64 * 4]; // [t][d][jq][b][4]  (64MB)
__device__ float g_emis[(size_t)512 * 64 * 9];        // [t][b][tau]
__device__ float g_llh[64];
__device__ int   g_cnt[1024];                         // sub-counters: [d*512 + sub*32]

// ---------------- packed f32x2 helpers (Blackwell FFMA2) ----------------
__device__ __forceinline__ unsigned long long ffma2(unsigned long long a,
                                                    unsigned long long b,
                                                    unsigned long long c) {
    unsigned long long d;
    asm("fma.rn.f32x2 %0, %1, %2, %3;" : "=l"(d) : "l"(a), "l"(b), "l"(c));
    return d;
}
__device__ __forceinline__ float hsum2(unsigned long long v) {
    float lo, hi;
    asm("mov.b64 {%0, %1}, %2;" : "=f"(lo), "=f"(hi) : "l"(v));
    return lo + hi;
}
__device__ __forceinline__ float tanh_ap(float x) {
    float y;
    asm("tanh.approx.f32 %0, %1;" : "=f"(y) : "f"(x));
    return y;
}
__device__ __forceinline__ float sig_ap(float x) {
    return 0.5f * tanh_ap(0.5f * x) + 0.5f;
}
__device__ __forceinline__ uint32_t tf32r(float x) {
    uint32_t r;
    asm("cvt.rna.tf32.f32 %0, %1;" : "=r"(r) : "f"(x));
    return r;
}

// ===========================================================================
// K1: fused embedding gather + input projection GEMM via tf32 mma.sync,
//   t-blocked x2 (R12 shape) with m16n8k8 (half the MMA instruction count).
//   grid (tg=256, ctile=16), 512 threads. Block = 128 c x 64 b x 2 t.
//   Dynamic smem: As 128x68 + Bs 2x64x68 u32 = 68KB.
// ===========================================================================
__global__ void __launch_bounds__(512) k_inproj(
    const int*   __restrict__ sent,
    const float* __restrict__ embed,
    const float* __restrict__ wih_f, const float* __restrict__ wih_b,
    const float* __restrict__ bih_f, const float* __restrict__ bhh_f,
    const float* __restrict__ bih_b, const float* __restrict__ bhh_b)
{
    extern __shared__ uint32_t smem_u32[];
    uint32_t* As = smem_u32;                 // [128][68]
    uint32_t* Bs = smem_u32 + 128 * 68;      // [2][64][68]
    __shared__ int words[2][64];

    const int tg    = blockIdx.x;
    const int ctile = blockIdx.y;
    const int d     = ctile >> 3;
    const int c0    = (ctile & 7) * 128;
    const int t0    = tg * 2;
    const int tid   = threadIdx.x;

    const float* __restrict__ wih = d ? wih_b : wih_f;
    const float* __restrict__ bih = d ? bih_b : bih_f;
    const float* __restrict__ bhh = d ? bhh_b : bhh_f;

    if (tid < 128) {
        int tt = tid >> 6, bb = tid & 63;
        words[tt][bb] = sent[bb * 512 + t0 + tt];
    }
    __syncthreads();

    const int w    = tid >> 5;
    const int lane = tid & 31;
    const int g    = lane >> 2;      // 0..7
    const int tg4  = lane & 3;       // 0..3
    const int cw   = (w & 7) * 16;
    const int bw   = (w >> 3) * 32;

    const int fra = tid >> 2;
    const int fq  = tid & 3;
    const int bt  = tid >> 8;
    const int frb = (tid >> 2) & 63;

    float acc[2][4][4];
    #pragma unroll
    for (int tt = 0; tt < 2; tt++)
        #pragma unroll
        for (int nt = 0; nt < 4; nt++)
            #pragma unroll
            for (int i = 0; i < 4; i++) acc[tt][nt][i] = 0.f;

    const float* __restrict__ wrow = wih + (size_t)(c0 + fra) * 300;
    const float* __restrict__ erow = embed + (size_t)words[bt][frb] * 300;

    for (int k0 = 0; k0 < 320; k0 += 64) {
        #pragma unroll
        for (int u = 0; u < 4; u++) {
            int q = fq + 4 * u;
            int k = k0 + q * 4;
            uint32_t va0 = 0, va1 = 0, va2 = 0, va3 = 0;
            uint32_t vb0 = 0, vb1 = 0, vb2 = 0, vb3 = 0;
            if (k < 300) {
                float4 av = *(const float4*)&wrow[k];
                float4 bv = *(const float4*)&erow[k];
                va0 = tf32r(av.x); va1 = tf32r(av.y);
                va2 = tf32r(av.z); va3 = tf32r(av.w);
                vb0 = tf32r(bv.x); vb1 = tf32r(bv.y);
                vb2 = tf32r(bv.z); vb3 = tf32r(bv.w);
            }
            *(uint4*)&As[fra * 68 + q * 4] = make_uint4(va0, va1, va2, va3);
            *(uint4*)&Bs[(bt * 64 + frb) * 68 + q * 4] =
                make_uint4(vb0, vb1, vb2, vb3);
        }
        __syncthreads();

        // ---- 8 k-steps of m16n8k8 (each covers 8 k) ----
        #pragma unroll
        for (int s = 0; s < 8; s++) {
            const int kk = s * 8;
            uint32_t a0 = As[(cw + g) * 68 + kk + tg4];
            uint32_t a1 = As[(cw + g + 8) * 68 + kk + tg4];
            uint32_t a2 = As[(cw + g) * 68 + kk + tg4 + 4];
            uint32_t a3 = As[(cw + g + 8) * 68 + kk + tg4 + 4];
            #pragma unroll
            for (int tt = 0; tt < 2; tt++) {
                #pragma unroll
                for (int nt = 0; nt < 4; nt++) {
                    const int brow = (tt * 64 + bw + nt * 8 + g) * 68 + kk;
                    uint32_t b0 = Bs[brow + tg4];
                    uint32_t b1 = Bs[brow + tg4 + 4];
                    asm volatile(
                        "mma.sync.aligned.m16n8k8.row.col.f32.tf32.tf32.f32 "
                        "{%0,%1,%2,%3}, {%4,%5,%6,%7}, {%8,%9}, {%0,%1,%2,%3};"
                        : "+f"(acc[tt][nt][0]), "+f"(acc[tt][nt][1]),
                          "+f"(acc[tt][nt][2]), "+f"(acc[tt][nt][3])
                        : "r"(a0), "r"(a1), "r"(a2), "r"(a3),
                          "r"(b0), "r"(b1));
                }
            }
        }
        __syncthreads();
    }

    const int cA = c0 + cw + g;
    const int cB = cA + 8;
    const float biasA = bih[cA] + bhh[cA];
    const float biasB = bih[cB] + bhh[cB];
    #pragma unroll
    for (int tt = 0; tt < 2; tt++) {
        const size_t obase = ((size_t)d * 512 + t0 + tt) * 65536;
        #pragma unroll
        for (int nt = 0; nt < 4; nt++) {
            const int bcol = bw + nt * 8 + 2 * tg4;
            float2 vA = make_float2(acc[tt][nt][0] + biasA,
                                    acc[tt][nt][1] + biasA);
            float2 vB = make_float2(acc[tt][nt][2] + biasB,
                                    acc[tt][nt][3] + biasB);
            *(float2*)&g_xp[obase + (size_t)cA * 64 + bcol] = vA;
            *(float2*)&g_xp[obase + (size_t)cB * 64 + bcol] = vB;
        }
    }
}

// ===========================================================================
// K2: persistent bidirectional LSTM recurrence — EXACT R12/R5 form
//   (measured best across 7 variants; frozen). 128 CTAs (64/dir), 256 thr.
// ===========================================================================
__global__ void __launch_bounds__(256, 1) k_rec(
    const float* __restrict__ whh_f, const float* __restrict__ whh_b)
{
    extern __shared__ float dsm[];
    float* wint   = dsm;            // 4096 floats (16KB): f4[(hcl*4+g)*64+jq]
    float* hstage = dsm + 4096;     // 16384 floats (64KB): f4[jq*64+b]

    const int bx  = blockIdx.x;
    const int d   = bx >> 6;
    const int m   = bx & 63;
    const int hc0 = m * 4;
    const int tid = threadIdx.x;
    const int hcl = tid >> 6;       // 0..3
    const int b   = tid & 63;
    const float* __restrict__ whh = d ? whh_b : whh_f;

    for (int q = tid; q < 1024; q += 256) {
        int row = q >> 6, jq = q & 63;
        int g = row & 3, hl = row >> 2;
        *(float4*)&wint[q * 4] =
            *(const float4*)&whh[(size_t)(g * 256 + hc0 + hl) * 256 + 4 * jq];
    }
    __syncthreads();

    const ulonglong2* __restrict__ w2 = (const ulonglong2*)wint;
    const float4* __restrict__ hst4 = (const float4*)hstage;
    const unsigned hstage_s = (unsigned)__cvta_generic_to_shared(hstage);
    const int wr0 = (hcl * 4 + 0) * 64;
    const int wr1 = (hcl * 4 + 1) * 64;
    const int wr2 = (hcl * 4 + 2) * 64;
    const int wr3 = (hcl * 4 + 3) * 64;

    int* __restrict__ cbase = &g_cnt[d * 512];

    float cstate = 0.f;

    const int tt_first = d ? 511 : 0;
    size_t xb = ((size_t)d * 512 + tt_first) * 65536;
    float xi = g_xp[xb + (size_t)(hc0 + hcl) * 64 + b];
    float xf = g_xp[xb + (size_t)(256 + hc0 + hcl) * 64 + b];
    float xg = g_xp[xb + (size_t)(512 + hc0 + hcl) * 64 + b];
    float xo = g_xp[xb + (size_t)(768 + hc0 + hcl) * 64 + b];

    for (int t = 0; t < 512; t++) {
        const int tt = d ? (511 - t) : t;

        float ai, af, ag, ao;

        if (t > 0) {
            if (tid == 0) {
                const int target = 64 * t;
                int s;
                do {
                    s = 0;
                    #pragma unroll
                    for (int i = 0; i < 8; i++) {
                        int v;
                        asm volatile("ld.relaxed.gpu.global.s32 %0, [%1];"
                                     : "=r"(v) : "l"(cbase + i * 32));
                        s += v;
                    }
                } while (s < target);
                int dummy;
                asm volatile("ld.acquire.gpu.global.s32 %0, [%1];"
                             : "=r"(dummy) : "l"(cbase) : "memory");
            }
            __syncthreads();

            const int hp = d ? (tt + 1) : (tt - 1);
            const float4* __restrict__ srcF4 =
                (const float4*)&g_hP[((size_t)hp * 2 + d) * 16384];

            #pragma unroll
            for (int q = 0; q < 4; q++) {
                #pragma unroll
                for (int r = 0; r < 4; r++) {
                    int f4i = q * 1024 + r * 256 + tid;
                    unsigned sa = hstage_s + (unsigned)f4i * 16u;
                    asm volatile("cp.async.cg.shared.global [%0], [%1], 16;"
                                 :: "r"(sa), "l"(srcF4 + f4i) : "memory");
                }
                asm volatile("cp.async.commit_group;" ::: "memory");
            }

            unsigned long long a0 = 0, a1 = 0, a2 = 0, a3 = 0;

            #define GEMM_CHUNK(Q, W)                                            \
                asm volatile("cp.async.wait_group %0;" :: "n"(W) : "memory");   \
                __syncthreads();                                                \
                _Pragma("unroll")                                               \
                for (int jq = (Q) * 16; jq < (Q) * 16 + 16; jq++) {             \
                    ulonglong2 h2 = *(const ulonglong2*)&hst4[jq * 64 + b];     \
                    ulonglong2 q0 = w2[wr0 + jq];                               \
                    ulonglong2 q1 = w2[wr1 + jq];                               \
                    ulonglong2 q2 = w2[wr2 + jq];                               \
                    ulonglong2 q3 = w2[wr3 + jq];                               \
                    a0 = ffma2(q0.x, h2.x, a0); a0 = ffma2(q0.y, h2.y, a0);     \
                    a1 = ffma2(q1.x, h2.x, a1); a1 = ffma2(q1.y, h2.y, a1);     \
                    a2 = ffma2(q2.x, h2.x, a2); a2 = ffma2(q2.y, h2.y, a2);     \
                    a3 = ffma2(q3.x, h2.x, a3); a3 = ffma2(q3.y, h2.y, a3);     \
                }
            GEMM_CHUNK(0, 3)
            GEMM_CHUNK(1, 2)
            GEMM_CHUNK(2, 1)
            GEMM_CHUNK(3, 0)
            #undef GEMM_CHUNK

            ai = hsum2(a0) + xi; af = hsum2(a1) + xf;
            ag = hsum2(a2) + xg; ao = hsum2(a3) + xo;
        } else {
            ai = xi; af = xf; ag = xg; ao = xo;
        }

        const float si = sig_ap(ai);
        const float sf = sig_ap(af);
        const float so = sig_ap(ao);
        cstate = sf * cstate + si * tanh_ap(ag);
        const float hval = so * tanh_ap(cstate);

        g_hP[((size_t)tt * 2 + d) * 16384 + (size_t)(m * 64 + b) * 4 + hcl] = hval;

        if (t < 511) {
            const int tn = d ? (510 - t) : (t + 1);
            const size_t xnb = ((size_t)d * 512 + tn) * 65536;
            xi = g_xp[xnb + (size_t)(hc0 + hcl) * 64 + b];
            xf = g_xp[xnb + (size_t)(256 + hc0 + hcl) * 64 + b];
            xg = g_xp[xnb + (size_t)(512 + hc0 + hcl) * 64 + b];
            xo = g_xp[xnb + (size_t)(768 + hc0 + hcl) * 64 + b];
        }

        __syncthreads();
        if (tid == 0) {
            asm volatile("red.release.gpu.global.add.s32 [%0], 1;"
                         :: "l"(cbase + (m & 7) * 32) : "memory");
        }
    }
}

// ===========================================================================
// K3: emissions from g_hP + barrier-counter reset for next graph replay.
// ===========================================================================
__global__ void __launch_bounds__(256) k_emis(
    const float* __restrict__ w_out, const float* __restrict__ b_out)
{
    if (blockIdx.x == 0 && threadIdx.x < 16)
        g_cnt[(threadIdx.x >> 3) * 512 + (threadIdx.x & 7) * 32] = 0;

    __shared__ float w_s[9 * 512];
    __shared__ float red[4][64][10];

    const int t = blockIdx.x, tid = threadIdx.x;
    for (int i = tid; i < 9 * 512; i += 256) w_s[i] = w_out[i];
    __syncthreads();

    const int b = tid & 63, seg = tid >> 6;
    const int d = seg >> 1, jq0 = (seg & 1) * 32;
    float acc[9] = {};
    const float4* __restrict__ hp4 =
        (const float4*)&g_hP[((size_t)t * 2 + d) * 16384];
    for (int jq = jq0; jq < jq0 + 32; jq++) {
        float4 h4 = hp4[jq * 64 + b];
        const int cb = d * 256 + 4 * jq;
        #pragma unroll
        for (int tau = 0; tau < 9; tau++) {
            acc[tau] += h4.x * w_s[tau * 512 + cb + 0]
                      + h4.y * w_s[tau * 512 + cb + 1]
                      + h4.z * w_s[tau * 512 + cb + 2]
                      + h4.w * w_s[tau * 512 + cb + 3];
        }
    }
    #pragma unroll
    for (int tau = 0; tau < 9; tau++) red[seg][b][tau] = acc[tau];
    __syncthreads();
    if (seg == 0) {
        #pragma unroll
        for (int tau = 0; tau < 9; tau++) {
            float v = red[0][b][tau] + red[1][b][tau] + red[2][b][tau] +
                      red[3][b][tau] + b_out[tau];
            g_emis[(size_t)t * 576 + b * 9 + tau] = v;
        }
    }
}

// ===========================================================================
// K4: CRF gold score + forward algorithm (logZ). grid 64 (b), 1 warp each.
//   Depth-4 register-ring prefetch of em/mask hides L2 latency.
// ===========================================================================
__global__ void k_crf(
    const int*   __restrict__ tags, const int* __restrict__ mask,
    const float* __restrict__ start_trans, const float* __restrict__ end_trans,
    const float* __restrict__ trans)
{
    const int b = blockIdx.x, lane = threadIdx.x;

    float sc = 0.f; int cnt = 0;
    for (int t = lane; t < 512; t += 32) {
        int mk = mask[b * 512 + t];
        cnt += mk;
        if (t >= 1 && mk) {
            int tp = tags[b * 512 + t - 1];
            int tc = tags[b * 512 + t];
            sc += trans[tp * 9 + tc] + g_emis[(size_t)t * 576 + b * 9 + tc];
        }
    }
    #pragma unroll
    for (int o = 16; o > 0; o >>= 1) {
        sc  += __shfl_down_sync(0xffffffffu, sc, o);
        cnt += __shfl_down_sync(0xffffffffu, cnt, o);
    }
    int len = __shfl_sync(0xffffffffu, cnt, 0);
    float score = 0.f;
    if (lane == 0) {
        int t0 = tags[b * 512];
        score = sc + start_trans[t0] + g_emis[b * 9 + t0];
        int tl = tags[b * 512 + len - 1];
        score += end_trans[tl];
    }

    float logZ = 0.f;
    if (lane < 9) {
        const int j = lane;
        float E[9];
        #pragma unroll
        for (int i = 0; i < 9; i++) E[i] = __expf(trans[i * 9 + j]);

        float a = start_trans[j] + g_emis[b * 9 + j];
        float a0 = __shfl_sync(0x1ffu, a, 0);
        float base = a0;
        a -= a0;

        float em_r[4]; int mk_r[4];
        #pragma unroll
        for (int i = 0; i < 4; i++) {
            int tt = 1 + i;
            em_r[i] = (tt < 512) ? g_emis[(size_t)tt * 576 + b * 9 + j] : 0.f;
            mk_r[i] = (tt < 512) ? mask[b * 512 + tt] : 0;
        }

        for (int t = 1; t < 512; t++) {
            const int k = (t - 1) & 3;
            const int   mk = mk_r[k];
            const float em = em_r[k];
            if (!mk) break;
            const int tp = t + 4;
            if (tp < 512) {
                em_r[k] = g_emis[(size_t)tp * 576 + b * 9 + j];
                mk_r[k] = mask[b * 512 + tp];
            } else {
                mk_r[k] = 0;
            }
            float ea = __expf(a);
            float s0 = 0.f, s1 = 0.f, s2 = 0.f;
            #pragma unroll
            for (int i = 0; i < 9; i += 3) {
                float e0 = __shfl_sync(0x1ffu, ea, i);
                float e1 = __shfl_sync(0x1ffu, ea, i + 1);
                float e2 = __shfl_sync(0x1ffu, ea, i + 2);
                s0 += e0 * E[i];
                s1 += e1 * E[i + 1];
                s2 += e2 * E[i + 2];
            }
            float u = __logf(s0 + s1 + s2) + em;
            float u0 = __shfl_sync(0x1ffu, u, 0);
            base += u0;
            a = u - u0;
        }
        float z = a + end_trans[j];
        float ez = __expf(z);
        float s = 0.f;
        #pragma unroll
        for (int i = 0; i < 9; i++) s += __shfl_sync(0x1ffu, ez, i);
        logZ = base + __logf(s);
    }
    if (lane == 0) g_llh[b] = score - logZ;
}

// ===========================================================================
// K5: final deterministic reduction  out = -mean(llh)
// ===========================================================================
__global__ void k_final(float* __restrict__ out)
{
    __shared__ float s[64];
    const int tid = threadIdx.x;
    s[tid] = g_llh[tid];
    __syncthreads();
    if (tid == 0) {
        float acc = 0.f;
        for (int i = 0; i < 64; i++) acc += s[i];
        out[0] = -acc / 64.f;
    }
}

// ===========================================================================
extern "C" void kernel_launch(void* const* d_in, const int* in_sizes, int n_in,
                              void* d_out, int out_size)
{
    const bool dictOrder = (in_sizes[2] == 15000000);
    const int ie = dictOrder ? 2 : 3;
    const int im = dictOrder ? 16 : 2;

    const int*   sent    = (const int*)  d_in[0];
    const int*   tags    = (const int*)  d_in[1];
    const float* embed   = (const float*)d_in[ie + 0];
    const float* wih_f   = (const float*)d_in[ie + 1];
    const float* whh_f   = (const float*)d_in[ie + 2];
    const float* bih_f   = (const float*)d_in[ie + 3];
    const float* bhh_f   = (const float*)d_in[ie + 4];
    const float* wih_b   = (const float*)d_in[ie + 5];
    const float* whh_b   = (const float*)d_in[ie + 6];
    const float* bih_b   = (const float*)d_in[ie + 7];
    const float* bhh_b   = (const float*)d_in[ie + 8];
    const float* w_out   = (const float*)d_in[ie + 9];
    const float* b_out   = (const float*)d_in[ie + 10];
    const float* s_tr    = (const float*)d_in[ie + 11];
    const float* e_tr    = (const float*)d_in[ie + 12];
    const float* trans   = (const float*)d_in[ie + 13];
    const int*   mask    = (const int*)  d_in[im];
    float*       out     = (float*)d_out;

    cudaFuncSetAttribute(k_rec, cudaFuncAttributeMaxDynamicSharedMemorySize, 81920);
    cudaFuncSetAttribute(k_inproj, cudaFuncAttributeMaxDynamicSharedMemorySize, 69632);

    dim3 g1(256, 16);
    k_inproj<<<g1, 512, 69632>>>(sent, embed, wih_f, wih_b, bih_f, bhh_f,
                                 bih_b, bhh_b);
    k_rec<<<128, 256, 81920>>>(whh_f, whh_b);
    k_emis<<<512, 256>>>(w_out, b_out);
    k_crf<<<64, 32>>>(tags, mask, s_tr, e_tr, trans);
    k_final<<<1, 64>>>(out);
}

// round 17
// speedup vs baseline: 1.5434x; 1.0271x over previous
#include <cuda_runtime.h>
#include <math.h>
#include <stdint.h>

// ---------------- device scratch ----------------
__device__ float g_xp[(size_t)2 * 512 * 1024 * 64];   // [dir][t][gate_row 0..1023][b]
__device__ float g_hP[(size_t)512 * 2 * 64 * 64 * 4]; // [t][d][jq][b][4]  (64MB)
__device__ float g_emis[(size_t)512 * 64 * 9];        // [t][b][tau]
__device__ float g_llh[64];
__device__ int   g_cnt[1024];                         // sub-counters: [d*512 + sub*32]

// ---------------- packed f32x2 helpers (Blackwell FFMA2) ----------------
__device__ __forceinline__ unsigned long long ffma2(unsigned long long a,
                                                    unsigned long long b,
                                                    unsigned long long c) {
    unsigned long long d;
    asm("fma.rn.f32x2 %0, %1, %2, %3;" : "=l"(d) : "l"(a), "l"(b), "l"(c));
    return d;
}
__device__ __forceinline__ float hsum2(unsigned long long v) {
    float lo, hi;
    asm("mov.b64 {%0, %1}, %2;" : "=f"(lo), "=f"(hi) : "l"(v));
    return lo + hi;
}
__device__ __forceinline__ float tanh_ap(float x) {
    float y;
    asm("tanh.approx.f32 %0, %1;" : "=f"(y) : "f"(x));
    return y;
}
__device__ __forceinline__ float sig_ap(float x) {
    return 0.5f * tanh_ap(0.5f * x) + 0.5f;
}
__device__ __forceinline__ uint32_t tf32r(float x) {
    uint32_t r;
    asm("cvt.rna.tf32.f32 %0, %1;" : "=r"(r) : "f"(x));
    return r;
}

// ===========================================================================
// K1: fused embedding gather + input projection GEMM via tf32 mma.sync,
//   t-blocked x2 with m16n8k8 (R15 form — proven).
// ===========================================================================
__global__ void __launch_bounds__(512) k_inproj(
    const int*   __restrict__ sent,
    const float* __restrict__ embed,
    const float* __restrict__ wih_f, const float* __restrict__ wih_b,
    const float* __restrict__ bih_f, const float* __restrict__ bhh_f,
    const float* __restrict__ bih_b, const float* __restrict__ bhh_b)
{
    extern __shared__ uint32_t smem_u32[];
    uint32_t* As = smem_u32;                 // [128][68]
    uint32_t* Bs = smem_u32 + 128 * 68;      // [2][64][68]
    __shared__ int words[2][64];

    const int tg    = blockIdx.x;
    const int ctile = blockIdx.y;
    const int d     = ctile >> 3;
    const int c0    = (ctile & 7) * 128;
    const int t0    = tg * 2;
    const int tid   = threadIdx.x;

    const float* __restrict__ wih = d ? wih_b : wih_f;
    const float* __restrict__ bih = d ? bih_b : bih_f;
    const float* __restrict__ bhh = d ? bhh_b : bhh_f;

    if (tid < 128) {
        int tt = tid >> 6, bb = tid & 63;
        words[tt][bb] = sent[bb * 512 + t0 + tt];
    }
    __syncthreads();

    const int w    = tid >> 5;
    const int lane = tid & 31;
    const int g    = lane >> 2;      // 0..7
    const int tg4  = lane & 3;       // 0..3
    const int cw   = (w & 7) * 16;
    const int bw   = (w >> 3) * 32;

    const int fra = tid >> 2;
    const int fq  = tid & 3;
    const int bt  = tid >> 8;
    const int frb = (tid >> 2) & 63;

    float acc[2][4][4];
    #pragma unroll
    for (int tt = 0; tt < 2; tt++)
        #pragma unroll
        for (int nt = 0; nt < 4; nt++)
            #pragma unroll
            for (int i = 0; i < 4; i++) acc[tt][nt][i] = 0.f;

    const float* __restrict__ wrow = wih + (size_t)(c0 + fra) * 300;
    const float* __restrict__ erow = embed + (size_t)words[bt][frb] * 300;

    for (int k0 = 0; k0 < 320; k0 += 64) {
        #pragma unroll
        for (int u = 0; u < 4; u++) {
            int q = fq + 4 * u;
            int k = k0 + q * 4;
            uint32_t va0 = 0, va1 = 0, va2 = 0, va3 = 0;
            uint32_t vb0 = 0, vb1 = 0, vb2 = 0, vb3 = 0;
            if (k < 300) {
                float4 av = *(const float4*)&wrow[k];
                float4 bv = *(const float4*)&erow[k];
                va0 = tf32r(av.x); va1 = tf32r(av.y);
                va2 = tf32r(av.z); va3 = tf32r(av.w);
                vb0 = tf32r(bv.x); vb1 = tf32r(bv.y);
                vb2 = tf32r(bv.z); vb3 = tf32r(bv.w);
            }
            *(uint4*)&As[fra * 68 + q * 4] = make_uint4(va0, va1, va2, va3);
            *(uint4*)&Bs[(bt * 64 + frb) * 68 + q * 4] =
                make_uint4(vb0, vb1, vb2, vb3);
        }
        __syncthreads();

        // ---- 8 k-steps of m16n8k8 ----
        #pragma unroll
        for (int s = 0; s < 8; s++) {
            const int kk = s * 8;
            uint32_t a0 = As[(cw + g) * 68 + kk + tg4];
            uint32_t a1 = As[(cw + g + 8) * 68 + kk + tg4];
            uint32_t a2 = As[(cw + g) * 68 + kk + tg4 + 4];
            uint32_t a3 = As[(cw + g + 8) * 68 + kk + tg4 + 4];
            #pragma unroll
            for (int tt = 0; tt < 2; tt++) {
                #pragma unroll
                for (int nt = 0; nt < 4; nt++) {
                    const int brow = (tt * 64 + bw + nt * 8 + g) * 68 + kk;
                    uint32_t b0 = Bs[brow + tg4];
                    uint32_t b1 = Bs[brow + tg4 + 4];
                    asm volatile(
                        "mma.sync.aligned.m16n8k8.row.col.f32.tf32.tf32.f32 "
                        "{%0,%1,%2,%3}, {%4,%5,%6,%7}, {%8,%9}, {%0,%1,%2,%3};"
                        : "+f"(acc[tt][nt][0]), "+f"(acc[tt][nt][1]),
                          "+f"(acc[tt][nt][2]), "+f"(acc[tt][nt][3])
                        : "r"(a0), "r"(a1), "r"(a2), "r"(a3),
                          "r"(b0), "r"(b1));
                }
            }
        }
        __syncthreads();
    }

    const int cA = c0 + cw + g;
    const int cB = cA + 8;
    const float biasA = bih[cA] + bhh[cA];
    const float biasB = bih[cB] + bhh[cB];
    #pragma unroll
    for (int tt = 0; tt < 2; tt++) {
        const size_t obase = ((size_t)d * 512 + t0 + tt) * 65536;
        #pragma unroll
        for (int nt = 0; nt < 4; nt++) {
            const int bcol = bw + nt * 8 + 2 * tg4;
            float2 vA = make_float2(acc[tt][nt][0] + biasA,
                                    acc[tt][nt][1] + biasA);
            float2 vB = make_float2(acc[tt][nt][2] + biasB,
                                    acc[tt][nt][3] + biasB);
            *(float2*)&g_xp[obase + (size_t)cA * 64 + bcol] = vA;
            *(float2*)&g_xp[obase + (size_t)cB * 64 + bcol] = vB;
        }
    }
}

// ===========================================================================
// K2: persistent bidirectional LSTM recurrence — EXACT R12/R5 form
//   (measured best across 7 variants; frozen). 128 CTAs (64/dir), 256 thr.
// ===========================================================================
__global__ void __launch_bounds__(256, 1) k_rec(
    const float* __restrict__ whh_f, const float* __restrict__ whh_b)
{
    extern __shared__ float dsm[];
    float* wint   = dsm;            // 4096 floats (16KB): f4[(hcl*4+g)*64+jq]
    float* hstage = dsm + 4096;     // 16384 floats (64KB): f4[jq*64+b]

    const int bx  = blockIdx.x;
    const int d   = bx >> 6;
    const int m   = bx & 63;
    const int hc0 = m * 4;
    const int tid = threadIdx.x;
    const int hcl = tid >> 6;       // 0..3
    const int b   = tid & 63;
    const float* __restrict__ whh = d ? whh_b : whh_f;

    for (int q = tid; q < 1024; q += 256) {
        int row = q >> 6, jq = q & 63;
        int g = row & 3, hl = row >> 2;
        *(float4*)&wint[q * 4] =
            *(const float4*)&whh[(size_t)(g * 256 + hc0 + hl) * 256 + 4 * jq];
    }
    __syncthreads();

    const ulonglong2* __restrict__ w2 = (const ulonglong2*)wint;
    const float4* __restrict__ hst4 = (const float4*)hstage;
    const unsigned hstage_s = (unsigned)__cvta_generic_to_shared(hstage);
    const int wr0 = (hcl * 4 + 0) * 64;
    const int wr1 = (hcl * 4 + 1) * 64;
    const int wr2 = (hcl * 4 + 2) * 64;
    const int wr3 = (hcl * 4 + 3) * 64;

    int* __restrict__ cbase = &g_cnt[d * 512];

    float cstate = 0.f;

    const int tt_first = d ? 511 : 0;
    size_t xb = ((size_t)d * 512 + tt_first) * 65536;
    float xi = g_xp[xb + (size_t)(hc0 + hcl) * 64 + b];
    float xf = g_xp[xb + (size_t)(256 + hc0 + hcl) * 64 + b];
    float xg = g_xp[xb + (size_t)(512 + hc0 + hcl) * 64 + b];
    float xo = g_xp[xb + (size_t)(768 + hc0 + hcl) * 64 + b];

    for (int t = 0; t < 512; t++) {
        const int tt = d ? (511 - t) : t;

        float ai, af, ag, ao;

        if (t > 0) {
            if (tid == 0) {
                const int target = 64 * t;
                int s;
                do {
                    s = 0;
                    #pragma unroll
                    for (int i = 0; i < 8; i++) {
                        int v;
                        asm volatile("ld.relaxed.gpu.global.s32 %0, [%1];"
                                     : "=r"(v) : "l"(cbase + i * 32));
                        s += v;
                    }
                } while (s < target);
                int dummy;
                asm volatile("ld.acquire.gpu.global.s32 %0, [%1];"
                             : "=r"(dummy) : "l"(cbase) : "memory");
            }
            __syncthreads();

            const int hp = d ? (tt + 1) : (tt - 1);
            const float4* __restrict__ srcF4 =
                (const float4*)&g_hP[((size_t)hp * 2 + d) * 16384];

            #pragma unroll
            for (int q = 0; q < 4; q++) {
                #pragma unroll
                for (int r = 0; r < 4; r++) {
                    int f4i = q * 1024 + r * 256 + tid;
                    unsigned sa = hstage_s + (unsigned)f4i * 16u;
                    asm volatile("cp.async.cg.shared.global [%0], [%1], 16;"
                                 :: "r"(sa), "l"(srcF4 + f4i) : "memory");
                }
                asm volatile("cp.async.commit_group;" ::: "memory");
            }

            unsigned long long a0 = 0, a1 = 0, a2 = 0, a3 = 0;

            #define GEMM_CHUNK(Q, W)                                            \
                asm volatile("cp.async.wait_group %0;" :: "n"(W) : "memory");   \
                __syncthreads();                                                \
                _Pragma("unroll")                                               \
                for (int jq = (Q) * 16; jq < (Q) * 16 + 16; jq++) {             \
                    ulonglong2 h2 = *(const ulonglong2*)&hst4[jq * 64 + b];     \
                    ulonglong2 q0 = w2[wr0 + jq];                               \
                    ulonglong2 q1 = w2[wr1 + jq];                               \
                    ulonglong2 q2 = w2[wr2 + jq];                               \
                    ulonglong2 q3 = w2[wr3 + jq];                               \
                    a0 = ffma2(q0.x, h2.x, a0); a0 = ffma2(q0.y, h2.y, a0);     \
                    a1 = ffma2(q1.x, h2.x, a1); a1 = ffma2(q1.y, h2.y, a1);     \
                    a2 = ffma2(q2.x, h2.x, a2); a2 = ffma2(q2.y, h2.y, a2);     \
                    a3 = ffma2(q3.x, h2.x, a3); a3 = ffma2(q3.y, h2.y, a3);     \
                }
            GEMM_CHUNK(0, 3)
            GEMM_CHUNK(1, 2)
            GEMM_CHUNK(2, 1)
            GEMM_CHUNK(3, 0)
            #undef GEMM_CHUNK

            ai = hsum2(a0) + xi; af = hsum2(a1) + xf;
            ag = hsum2(a2) + xg; ao = hsum2(a3) + xo;
        } else {
            ai = xi; af = xf; ag = xg; ao = xo;
        }

        const float si = sig_ap(ai);
        const float sf = sig_ap(af);
        const float so = sig_ap(ao);
        cstate = sf * cstate + si * tanh_ap(ag);
        const float hval = so * tanh_ap(cstate);

        g_hP[((size_t)tt * 2 + d) * 16384 + (size_t)(m * 64 + b) * 4 + hcl] = hval;

        if (t < 511) {
            const int tn = d ? (510 - t) : (t + 1);
            const size_t xnb = ((size_t)d * 512 + tn) * 65536;
            xi = g_xp[xnb + (size_t)(hc0 + hcl) * 64 + b];
            xf = g_xp[xnb + (size_t)(256 + hc0 + hcl) * 64 + b];
            xg = g_xp[xnb + (size_t)(512 + hc0 + hcl) * 64 + b];
            xo = g_xp[xnb + (size_t)(768 + hc0 + hcl) * 64 + b];
        }

        __syncthreads();
        if (tid == 0) {
            asm volatile("red.release.gpu.global.add.s32 [%0], 1;"
                         :: "l"(cbase + (m & 7) * 32) : "memory");
        }
    }
}

// ===========================================================================
// K3: emissions from g_hP + barrier-counter reset for next graph replay.
// ===========================================================================
__global__ void __launch_bounds__(256) k_emis(
    const float* __restrict__ w_out, const float* __restrict__ b_out)
{
    if (blockIdx.x == 0 && threadIdx.x < 16)
        g_cnt[(threadIdx.x >> 3) * 512 + (threadIdx.x & 7) * 32] = 0;

    __shared__ float w_s[9 * 512];
    __shared__ float red[4][64][10];

    const int t = blockIdx.x, tid = threadIdx.x;
    for (int i = tid; i < 9 * 512; i += 256) w_s[i] = w_out[i];
    __syncthreads();

    const int b = tid & 63, seg = tid >> 6;
    const int d = seg >> 1, jq0 = (seg & 1) * 32;
    float acc[9] = {};
    const float4* __restrict__ hp4 =
        (const float4*)&g_hP[((size_t)t * 2 + d) * 16384];
    for (int jq = jq0; jq < jq0 + 32; jq++) {
        float4 h4 = hp4[jq * 64 + b];
        const int cb = d * 256 + 4 * jq;
        #pragma unroll
        for (int tau = 0; tau < 9; tau++) {
            acc[tau] += h4.x * w_s[tau * 512 + cb + 0]
                      + h4.y * w_s[tau * 512 + cb + 1]
                      + h4.z * w_s[tau * 512 + cb + 2]
                      + h4.w * w_s[tau * 512 + cb + 3];
        }
    }
    #pragma unroll
    for (int tau = 0; tau < 9; tau++) red[seg][b][tau] = acc[tau];
    __syncthreads();
    if (seg == 0) {
        #pragma unroll
        for (int tau = 0; tau < 9; tau++) {
            float v = red[0][b][tau] + red[1][b][tau] + red[2][b][tau] +
                      red[3][b][tau] + b_out[tau];
            g_emis[(size_t)t * 576 + b * 9 + tau] = v;
        }
    }
}

// ===========================================================================
// K4: CRF gold score + forward algorithm (logZ). grid 64 (b), 1 warp each.
//   R5 form: scalar one-step lookahead (NO register-array indexing).
// ===========================================================================
__global__ void k_crf(
    const int*   __restrict__ tags, const int* __restrict__ mask,
    const float* __restrict__ start_trans, const float* __restrict__ end_trans,
    const float* __restrict__ trans)
{
    const int b = blockIdx.x, lane = threadIdx.x;

    float sc = 0.f; int cnt = 0;
    for (int t = lane; t < 512; t += 32) {
        int mk = mask[b * 512 + t];
        cnt += mk;
        if (t >= 1 && mk) {
            int tp = tags[b * 512 + t - 1];
            int tc = tags[b * 512 + t];
            sc += trans[tp * 9 + tc] + g_emis[(size_t)t * 576 + b * 9 + tc];
        }
    }
    #pragma unroll
    for (int o = 16; o > 0; o >>= 1) {
        sc  += __shfl_down_sync(0xffffffffu, sc, o);
        cnt += __shfl_down_sync(0xffffffffu, cnt, o);
    }
    int len = __shfl_sync(0xffffffffu, cnt, 0);
    float score = 0.f;
    if (lane == 0) {
        int t0 = tags[b * 512];
        score = sc + start_trans[t0] + g_emis[b * 9 + t0];
        int tl = tags[b * 512 + len - 1];
        score += end_trans[tl];
    }

    float logZ = 0.f;
    if (lane < 9) {
        const int j = lane;
        float E[9];
        #pragma unroll
        for (int i = 0; i < 9; i++) E[i] = __expf(trans[i * 9 + j]);

        float a = start_trans[j] + g_emis[b * 9 + j];
        float a0 = __shfl_sync(0x1ffu, a, 0);
        float base = a0;
        a -= a0;

        float em_n = g_emis[(size_t)576 + b * 9 + j];
        int   mk_n = mask[b * 512 + 1];

        for (int t = 1; t < 512; t++) {
            if (!mk_n) break;                  // mask is a contiguous prefix
            float em = em_n;
            if (t < 511) {
                em_n = g_emis[(size_t)(t + 1) * 576 + b * 9 + j];
                mk_n = mask[b * 512 + t + 1];
            } else {
                mk_n = 0;
            }
            float ea = __expf(a);
            float s0 = 0.f, s1 = 0.f, s2 = 0.f;
            #pragma unroll
            for (int i = 0; i < 9; i += 3) {
                float e0 = __shfl_sync(0x1ffu, ea, i);
                float e1 = __shfl_sync(0x1ffu, ea, i + 1);
                float e2 = __shfl_sync(0x1ffu, ea, i + 2);
                s0 += e0 * E[i];
                s1 += e1 * E[i + 1];
                s2 += e2 * E[i + 2];
            }
            float u = __logf(s0 + s1 + s2) + em;
            float u0 = __shfl_sync(0x1ffu, u, 0);
            base += u0;
            a = u - u0;
        }
        float z = a + end_trans[j];
        float ez = __expf(z);
        float s = 0.f;
        #pragma unroll
        for (int i = 0; i < 9; i++) s += __shfl_sync(0x1ffu, ez, i);
        logZ = base + __logf(s);
    }
    if (lane == 0) g_llh[b] = score - logZ;
}

// ===========================================================================
// K5: final deterministic reduction  out = -mean(llh)
// ===========================================================================
__global__ void k_final(float* __restrict__ out)
{
    __shared__ float s[64];
    const int tid = threadIdx.x;
    s[tid] = g_llh[tid];
    __syncthreads();
    if (tid == 0) {
        float acc = 0.f;
        for (int i = 0; i < 64; i++) acc += s[i];
        out[0] = -acc / 64.f;
    }
}

// ===========================================================================
extern "C" void kernel_launch(void* const* d_in, const int* in_sizes, int n_in,
                              void* d_out, int out_size)
{
    const bool dictOrder = (in_sizes[2] == 15000000);
    const int ie = dictOrder ? 2 : 3;
    const int im = dictOrder ? 16 : 2;

    const int*   sent    = (const int*)  d_in[0];
    const int*   tags    = (const int*)  d_in[1];
    const float* embed   = (const float*)d_in[ie + 0];
    const float* wih_f   = (const float*)d_in[ie + 1];
    const float* whh_f   = (const float*)d_in[ie + 2];
    const float* bih_f   = (const float*)d_in[ie + 3];
    const float* bhh_f   = (const float*)d_in[ie + 4];
    const float* wih_b   = (const float*)d_in[ie + 5];
    const float* whh_b   = (const float*)d_in[ie + 6];
    const float* bih_b   = (const float*)d_in[ie + 7];
    const float* bhh_b   = (const float*)d_in[ie + 8];
    const float* w_out   = (const float*)d_in[ie + 9];
    const float* b_out   = (const float*)d_in[ie + 10];
    const float* s_tr    = (const float*)d_in[ie + 11];
    const float* e_tr    = (const float*)d_in[ie + 12];
    const float* trans   = (const float*)d_in[ie + 13];
    const int*   mask    = (const int*)  d_in[im];
    float*       out     = (float*)d_out;

    cudaFuncSetAttribute(k_rec, cudaFuncAttributeMaxDynamicSharedMemorySize, 81920);
    cudaFuncSetAttribute(k_inproj, cudaFuncAttributeMaxDynamicSharedMemorySize, 69632);

    dim3 g1(256, 16);
    k_inproj<<<g1, 512, 69632>>>(sent, embed, wih_f, wih_b, bih_f, bhh_f,
                                 bih_b, bhh_b);
    k_rec<<<128, 256, 81920>>>(whh_f, whh_b);
    k_emis<<<512, 256>>>(w_out, b_out);
    k_crf<<<64, 32>>>(tags, mask, s_tr, e_tr, trans);
    k_final<<<1, 64>>>(out);
}